// round 11
// baseline (speedup 1.0000x reference)
#include <cuda_runtime.h>
#include <cuda_fp16.h>
#include <cstdint>
#include <cstddef>
#include <cstring>

#define N_NODES 8192
#define D 128
#define MT 128                       // M rows per CTA
#define NSPLIT 4
#define KSPLIT (N_NODES / NSPLIT)    // 2048
#define KCG 64                       // K per pipeline stage
#define NITER_S (KSPLIT / KCG)       // 32
#define A_TILE_B (MT * KCG * 2)          // 16384
#define B_TILE_B (KCG * D * 2)           // 16384
#define STAGE_B (A_TILE_B + B_TILE_B)    // 32768
#define SMEM_BYTES (3 * STAGE_B)         // 98304 (3-slot ring, occ 2)

// ---------------- device scratch ----------------
__device__ float g_dinv[N_NODES];
__device__ __half g_ah[(size_t)N_NODES * N_NODES];   // fp16 copy of adj (128MB)
__device__ __half g_h[(size_t)N_NODES * D];          // dinv-scaled proj, fp16 [k][n]
__device__ float g_part[(size_t)NSPLIT * N_NODES * D];  // split-K partials (16MB)

// ---------------- helpers ----------------
__device__ __forceinline__ uint32_t smem_u32(const void* p) {
    uint32_t a;
    asm("{ .reg .u64 t; cvta.to.shared.u64 t, %1; cvt.u32.u64 %0, t; }" : "=r"(a) : "l"(p));
    return a;
}
__device__ __forceinline__ void cp_async16(uint32_t dst, const void* src) {
    asm volatile("cp.async.cg.shared.global [%0], [%1], 16;" :: "r"(dst), "l"(src));
}
__device__ __forceinline__ void cp_commit() {
    asm volatile("cp.async.commit_group;" ::: "memory");
}
__device__ __forceinline__ void cp_wait1() {
    asm volatile("cp.async.wait_group 1;" ::: "memory");
}
__device__ __forceinline__ void ldsm_x4(uint32_t* r, uint32_t a) {
    asm volatile("ldmatrix.sync.aligned.m8n8.x4.shared.b16 {%0,%1,%2,%3}, [%4];"
                 : "=r"(r[0]), "=r"(r[1]), "=r"(r[2]), "=r"(r[3]) : "r"(a));
}
__device__ __forceinline__ void ldsm_x4_t(uint32_t* r, uint32_t a) {
    asm volatile("ldmatrix.sync.aligned.m8n8.x4.trans.shared.b16 {%0,%1,%2,%3}, [%4];"
                 : "=r"(r[0]), "=r"(r[1]), "=r"(r[2]), "=r"(r[3]) : "r"(a));
}
__device__ __forceinline__ void mma16816(float* c, const uint32_t* a, uint32_t b0, uint32_t b1) {
    asm volatile(
        "mma.sync.aligned.m16n8k16.row.col.f32.f16.f16.f32 "
        "{%0,%1,%2,%3},{%4,%5,%6,%7},{%8,%9},{%0,%1,%2,%3};"
        : "+f"(c[0]), "+f"(c[1]), "+f"(c[2]), "+f"(c[3])
        : "r"(a[0]), "r"(a[1]), "r"(a[2]), "r"(a[3]), "r"(b0), "r"(b1));
}
__device__ __forceinline__ uint32_t h2u(__half2 h) {
    uint32_t u; __builtin_memcpy(&u, &h, 4); return u;
}

// ---------------------------------------------------------------------------
// Kernel 0: fused rowsum + fp16 convert of adj (82-84% DRAM — near roofline)
// ---------------------------------------------------------------------------
__global__ void __launch_bounds__(256) rowsum_cvt_kernel(const float* __restrict__ adj) {
    int row = blockIdx.x;
    const float4* p = reinterpret_cast<const float4*>(adj + (size_t)row * N_NODES);
    uint2* q = reinterpret_cast<uint2*>(g_ah + (size_t)row * N_NODES);
    float s = 0.f;
    #pragma unroll 8
    for (int i = threadIdx.x; i < N_NODES / 4; i += 256) {
        float4 v = p[i];
        s += (v.x + v.y) + (v.z + v.w);
        uint2 h;
        h.x = h2u(__floats2half2_rn(v.x, v.y));
        h.y = h2u(__floats2half2_rn(v.z, v.w));
        q[i] = h;
    }
    #pragma unroll
    for (int o = 16; o > 0; o >>= 1) s += __shfl_down_sync(0xffffffffu, s, o);
    __shared__ float red[8];
    int lane = threadIdx.x & 31, wid = threadIdx.x >> 5;
    if (lane == 0) red[wid] = s;
    __syncthreads();
    if (wid == 0) {
        s = (lane < 8) ? red[lane] : 0.f;
        #pragma unroll
        for (int o = 4; o > 0; o >>= 1) s += __shfl_down_sync(0xffffffffu, s, o);
        if (lane == 0) g_dinv[row] = (s > 0.f) ? rsqrtf(s) : 0.f;
    }
}

// ---------------------------------------------------------------------------
// Kernel 1: g_h[k][n] = fp16( dinv[k] * (x[k,:] @ W)[n] )
// ---------------------------------------------------------------------------
__global__ void __launch_bounds__(256) proj_kernel(const float* __restrict__ x,
                                                   const float* __restrict__ w) {
    __shared__ float xs[32][D];
    int row0 = blockIdx.x * 32;
    int tid = threadIdx.x;
    for (int i = tid; i < 32 * D; i += 256)
        xs[i / D][i % D] = x[(size_t)(row0 + i / D) * D + (i % D)];
    __syncthreads();

    int d = tid & 127;
    int half_ = tid >> 7;
    float acc[16];
    #pragma unroll
    for (int r = 0; r < 16; r++) acc[r] = 0.f;

    for (int k = 0; k < D; k++) {
        float wv = w[k * D + d];
        #pragma unroll
        for (int r = 0; r < 16; r++)
            acc[r] += xs[half_ * 16 + r][k] * wv;
    }
    #pragma unroll
    for (int r = 0; r < 16; r++) {
        int row = row0 + half_ * 16 + r;
        g_h[(size_t)row * D + d] = __float2half(acc[r] * g_dinv[row]);
    }
}

// ---------------------------------------------------------------------------
// Kernel 2: fp16 GEMM partials via mma.sync (fp32 accum), split-K=4.
// grid (64,4): CTA = M128 x N128 x K2048. 256 threads, 8 warps 4(M)x2(N),
// warp tile 32x64, occ 2. 3-slot static ring:
//   wait_group 1 ; sync ; issue stage i+2 -> slot (i+2)%3 ; commit ; compute i.
// ---------------------------------------------------------------------------
__global__ void __launch_bounds__(256, 2) gemm_kernel() {
    extern __shared__ __align__(16) unsigned char smbuf[];
    const uint32_t sm = smem_u32(smbuf);

    const int tid = threadIdx.x;
    const int lane = tid & 31;
    const int wid = tid >> 5;
    const int wr = wid & 3;          // warp row  (32 rows)
    const int wc = wid >> 2;         // warp col  (64 cols)
    const int row0 = blockIdx.x * MT;
    const int kb0 = blockIdx.y * KSPLIT;

    // ---- A loader: 4 cp.async16 per thread (128 rows x 64 k fp16 = 16KB) ----
    const int ar = tid >> 1;                 // 0..127 row
    const int ah = tid & 1;                  // 64B half of the 128B row
    uint32_t a_off[4];
    #pragma unroll
    for (int j = 0; j < 4; j++)
        a_off[j] = ((uint32_t)ar * 128 + ah * 64 + j * 16) ^ ((uint32_t)(ar & 7) << 4);
    const __half* asrc = g_ah + (size_t)(row0 + ar) * N_NODES + kb0 + ah * 32;

    // ---- B loader: 4 cp.async16 per thread (64 k x 128 n fp16 = 16KB) ----
    const int bk = tid >> 2;
    const int bnc0 = (tid & 3) * 4;
    uint32_t b_off[4];
    #pragma unroll
    for (int j = 0; j < 4; j++)
        b_off[j] = (((uint32_t)bk * D + (bnc0 + j) * 8) * 2) ^ ((uint32_t)(bk & 7) << 4);
    const __half* bsrc = g_h + (size_t)(kb0 + bk) * D + bnc0 * 8;

    // ---- mma fragment addressing ----
    const uint32_t axor_f = (uint32_t)((lane & 15) & 7) << 4;
    const uint32_t aoff_m0 = (((uint32_t)(wr * 32 + (lane & 15)) * KCG + (lane >> 4) * 8) * 2);
    const uint32_t aoff_m1 = aoff_m0 + 16u * KCG * 2;   // +16 rows
    const int brow_l = (lane & 7) + ((lane >> 3) & 1) * 8;
    const uint32_t bxor_f = (uint32_t)(lane & 7) << 4;
    const uint32_t boff_l = ((uint32_t)brow_l * D + wc * 64 + (lane >> 4) * 8) * 2;
    const int n0w = wc * 64;

    float c[16][4];
    #pragma unroll
    for (int j = 0; j < 16; j++)
        #pragma unroll
        for (int q = 0; q < 4; q++) c[j][q] = 0.f;

    #define ISSUE_STAGE(base, p)                                                   \
        do {                                                                       \
            const __half* _ap = asrc + (size_t)(p) * KCG;                          \
            cp_async16((base) + a_off[0], _ap);                                    \
            cp_async16((base) + a_off[1], _ap + 8);                                \
            cp_async16((base) + a_off[2], _ap + 16);                               \
            cp_async16((base) + a_off[3], _ap + 24);                               \
            const __half* _bp = bsrc + (size_t)(p) * KCG * D;                      \
            cp_async16((base) + A_TILE_B + b_off[0], _bp);                         \
            cp_async16((base) + A_TILE_B + b_off[1], _bp + 8);                     \
            cp_async16((base) + A_TILE_B + b_off[2], _bp + 16);                    \
            cp_async16((base) + A_TILE_B + b_off[3], _bp + 24);                    \
        } while (0)

    #define COMPUTE_STAGE(sA, sB)                                                  \
        do {                                                                       \
            _Pragma("unroll")                                                      \
            for (int s16 = 0; s16 < 4; s16++) {                                    \
                uint32_t ra0[4], ra1[4];                                           \
                ldsm_x4(ra0, (sA) + ((aoff_m0 + 32u * s16) ^ axor_f));             \
                ldsm_x4(ra1, (sA) + ((aoff_m1 + 32u * s16) ^ axor_f));             \
                uint32_t rb[4][4];                                                 \
                _Pragma("unroll")                                                  \
                for (int nb = 0; nb < 4; nb++)                                     \
                    ldsm_x4_t(rb[nb],                                              \
                        (sB) + ((boff_l + 4096u * s16 + 32u * nb) ^ bxor_f));      \
                _Pragma("unroll")                                                  \
                for (int nb = 0; nb < 4; nb++) {                                   \
                    mma16816(c[nb * 2 + 0], ra0, rb[nb][0], rb[nb][1]);            \
                    mma16816(c[nb * 2 + 1], ra0, rb[nb][2], rb[nb][3]);            \
                    mma16816(c[8 + nb * 2 + 0], ra1, rb[nb][0], rb[nb][1]);        \
                    mma16816(c[8 + nb * 2 + 1], ra1, rb[nb][2], rb[nb][3]);        \
                }                                                                  \
            }                                                                      \
        } while (0)

    #define STEP(slot_issue, slot_comp, p_issue)                                   \
        do {                                                                       \
            cp_wait1();                                                            \
            __syncthreads();                                                       \
            if ((p_issue) < NITER_S) ISSUE_STAGE(slot_issue, p_issue);             \
            cp_commit();                                                           \
            COMPUTE_STAGE(slot_comp, (slot_comp) + A_TILE_B);                      \
        } while (0)

    const uint32_t s0 = sm;
    const uint32_t s1 = sm + STAGE_B;
    const uint32_t s2 = sm + 2 * STAGE_B;

    // ---- prologue: fill 2 stages ----
    ISSUE_STAGE(s0, 0); cp_commit();
    ISSUE_STAGE(s1, 1); cp_commit();

    // ---- main loop: 10 x 3 stages + 2 tail (32 stages total) ----
    for (int j = 0; j < 10; j++) {
        const int p = 3 * j;
        STEP(s2, s0, p + 2);     // compute stage p   (slot0), issue p+2 -> slot2
        STEP(s0, s1, p + 3);     // compute stage p+1 (slot1), issue p+3 -> slot0
        STEP(s1, s2, p + 4);     // compute stage p+2 (slot2), issue p+4 -> slot1
    }
    STEP(s2, s0, 32);            // stage 30 (slot0), no issue
    STEP(s0, s1, 33);            // stage 31 (slot1), no issue

    // ---- epilogue: raw fp32 partials -> g_part[by] ----
    float* part = g_part + (size_t)blockIdx.y * N_NODES * D;
    const int grp = lane >> 2, tid4 = lane & 3;
    #pragma unroll
    for (int mf = 0; mf < 2; mf++) {
        const int r1 = row0 + wr * 32 + mf * 16 + grp;
        const int r2 = r1 + 8;
        #pragma unroll
        for (int j = 0; j < 4; j++) {
            // two n8 frags per j stored together (cols j*16 .. j*16+15)
            int col = n0w + j * 16 + tid4 * 2;
            float2 o1a, o1b, o2a, o2b;
            o1a.x = c[mf * 8 + j * 2 + 0][0];
            o1a.y = c[mf * 8 + j * 2 + 0][1];
            o2a.x = c[mf * 8 + j * 2 + 0][2];
            o2a.y = c[mf * 8 + j * 2 + 0][3];
            o1b.x = c[mf * 8 + j * 2 + 1][0];
            o1b.y = c[mf * 8 + j * 2 + 1][1];
            o2b.x = c[mf * 8 + j * 2 + 1][2];
            o2b.y = c[mf * 8 + j * 2 + 1][3];
            *reinterpret_cast<float2*>(part + (size_t)r1 * D + col) = o1a;
            *reinterpret_cast<float2*>(part + (size_t)r1 * D + col + 8) = o1b;
            *reinterpret_cast<float2*>(part + (size_t)r2 * D + col) = o2a;
            *reinterpret_cast<float2*>(part + (size_t)r2 * D + col + 8) = o2b;
        }
    }
    #undef ISSUE_STAGE
    #undef COMPUTE_STAGE
    #undef STEP
}

// ---------------------------------------------------------------------------
// Kernel 3: out = dinv * (P0 + P1 + P2 + P3) + bias
// ---------------------------------------------------------------------------
__global__ void __launch_bounds__(256) combine_kernel(const float* __restrict__ bias,
                                                      float* __restrict__ out) {
    int idx = blockIdx.x * 256 + threadIdx.x;      // over 8192*32 float4s
    int row = idx >> 5;
    int c4 = idx & 31;
    const float4* p0 = reinterpret_cast<const float4*>(g_part);
    const float4* p1 = reinterpret_cast<const float4*>(g_part + (size_t)N_NODES * D);
    const float4* p2 = reinterpret_cast<const float4*>(g_part + (size_t)2 * N_NODES * D);
    const float4* p3 = reinterpret_cast<const float4*>(g_part + (size_t)3 * N_NODES * D);
    float4 a = p0[idx], b = p1[idx], e = p2[idx], f = p3[idx];
    float di = g_dinv[row];
    float4 bv = reinterpret_cast<const float4*>(bias)[c4];
    float4 o;
    o.x = fmaf((a.x + b.x) + (e.x + f.x), di, bv.x);
    o.y = fmaf((a.y + b.y) + (e.y + f.y), di, bv.y);
    o.z = fmaf((a.z + b.z) + (e.z + f.z), di, bv.z);
    o.w = fmaf((a.w + b.w) + (e.w + f.w), di, bv.w);
    reinterpret_cast<float4*>(out)[idx] = o;
}

// ---------------------------------------------------------------------------
extern "C" void kernel_launch(void* const* d_in, const int* in_sizes, int n_in,
                              void* d_out, int out_size) {
    const float* x = nullptr;
    const float* adj = nullptr;
    const float* weight = nullptr;
    const float* bias = nullptr;
    for (int i = 0; i < n_in; i++) {
        long long sz = in_sizes[i];
        if (sz == (long long)N_NODES * N_NODES) adj = (const float*)d_in[i];
        else if (sz == (long long)N_NODES * D)  x = (const float*)d_in[i];
        else if (sz == (long long)D * D)        weight = (const float*)d_in[i];
        else if (sz == D)                       bias = (const float*)d_in[i];
    }
    float* out = (float*)d_out;

    cudaFuncSetAttribute(gemm_kernel,
                         cudaFuncAttributeMaxDynamicSharedMemorySize, SMEM_BYTES);

    rowsum_cvt_kernel<<<N_NODES, 256>>>(adj);
    proj_kernel<<<N_NODES / 32, 256>>>(x, weight);
    gemm_kernel<<<dim3(N_NODES / MT, NSPLIT), 256, SMEM_BYTES>>>();
    combine_kernel<<<N_NODES * D / 4 / 256, 256>>>(bias, out);
}